// round 5
// baseline (speedup 1.0000x reference)
#include <cuda_runtime.h>

#define N_NODES 50000
#define N_EDGES 200000
#define OUTD 32
#define IN_SELF 128
#define EDGE_DIM 16

#define EDGE_BLOCKS 296
#define EDGE_THREADS 512

// Node GEMM: block tile 128 nodes x 32 chans, K=160 in 10 chunks of 16.
// 128 threads; each thread owns 8 nodes x 4 chans as 4x4 packed f32x2 accs.
#define BN 128
#define KB 16
#define BNP 132
#define NT 128

__device__ float g_scratch[N_NODES * OUTD + N_NODES];

__device__ __forceinline__ void red_add_v4(float* ptr, float4 v) {
    asm volatile("red.global.add.v4.f32 [%0], {%1, %2, %3, %4};"
                 :: "l"(ptr), "f"(v.x), "f"(v.y), "f"(v.z), "f"(v.w)
                 : "memory");
}

__device__ __forceinline__ void fma2(unsigned long long& d,
                                     unsigned long long a,
                                     unsigned long long b) {
    asm("fma.rn.f32x2 %0, %1, %2, %0;" : "+l"(d) : "l"(a), "l"(b));
}

// ---------------------------------------------------------------------------
// Edge kernel (unchanged, proven): per-block Wsum reduction, 4 edges/warp,
// 8 lanes/edge, 4 channels/lane, RED.128 into agg.
// ---------------------------------------------------------------------------
__global__ void __launch_bounds__(EDGE_THREADS)
edge_kernel(const float* __restrict__ h_neigh,
            const float* __restrict__ edge_features,
            const float* __restrict__ W_edge,
            const float* __restrict__ b_edge,
            const int* __restrict__ src,
            const int* __restrict__ dst) {
    __shared__ __align__(16) float sW[EDGE_DIM * OUTD];
    __shared__ __align__(16) float sb[OUTD];
    {
        int t = threadIdx.x;
        int j = t >> 4, k = t & 15;
        float s = 0.f;
        #pragma unroll
        for (int i = 0; i < OUTD; i++)
            s += W_edge[(i * OUTD + j) * EDGE_DIM + k];
        sW[k * OUTD + j] = s;
        if (t < OUTD) {
            float s2 = 0.f;
            #pragma unroll
            for (int i = 0; i < OUTD; i++)
                s2 += b_edge[i * OUTD + t];
            sb[t] = s2;
        }
    }
    __syncthreads();

    float* g_agg = g_scratch;
    float* g_deg = g_scratch + N_NODES * OUTD;

    const int lane = threadIdx.x & 31;
    const int warp = threadIdx.x >> 5;
    const int g = lane >> 3;
    const int p = lane & 7;
    const int wpb = EDGE_THREADS >> 5;
    const int nwarps = EDGE_BLOCKS * wpb;
    const int NGROUPS = N_EDGES / 4;

    for (int grp = blockIdx.x * wpb + warp; grp < NGROUPS; grp += nwarps) {
        int e0 = grp * 4;
        int e = e0 + g;
        int s = src[e];
        int d = dst[e];

        float2 ef = *reinterpret_cast<const float2*>(
            &edge_features[e0 * EDGE_DIM + lane * 2]);

        float4 acc = *reinterpret_cast<const float4*>(&sb[4 * p]);
        #pragma unroll
        for (int k = 0; k < EDGE_DIM; k++) {
            float ek = __shfl_sync(0xffffffffu, (k & 1) ? ef.y : ef.x, k >> 1, 8);
            float4 w = *reinterpret_cast<const float4*>(&sW[k * OUTD + 4 * p]);
            acc.x = fmaf(ek, w.x, acc.x);
            acc.y = fmaf(ek, w.y, acc.y);
            acc.z = fmaf(ek, w.z, acc.z);
            acc.w = fmaf(ek, w.w, acc.w);
        }

        float4 hv = *reinterpret_cast<const float4*>(&h_neigh[s * OUTD + 4 * p]);
        float4 msg = make_float4(hv.x * acc.x, hv.y * acc.y,
                                 hv.z * acc.z, hv.w * acc.w);
        red_add_v4(&g_agg[d * OUTD + 4 * p], msg);
        if (p == 0) atomicAdd(&g_deg[d], 1.0f);
    }
}

// ---------------------------------------------------------------------------
// Node kernel: double-buffered GEMM with packed fma.rn.f32x2.
//   out[n,c] = relu( X[n,:] . Wc[c,:] ),  X=[h_self | agg/deg], K=160.
// h staged transposed h_s[k][node]; w staged DUPLICATED w_d[k][2c]=w_d[k][2c+1]
// so both fma2 operands load as packed pairs (no PACK instructions).
// ---------------------------------------------------------------------------
__global__ void __launch_bounds__(NT, 6)
node_kernel(const float* __restrict__ h_self,
            const float* __restrict__ W_self,
            const float* __restrict__ W_neigh,
            float* __restrict__ out) {
    __shared__ __align__(16) float h_s[2][KB][BNP];
    __shared__ __align__(16) float w_d[2][KB][2 * OUTD];
    __shared__ float sinv[BN];

    const float* g_agg = g_scratch;
    const float* g_deg = g_scratch + N_NODES * OUTD;

    const int t = threadIdx.x;
    const int nbase = blockIdx.x * BN;
    const int tn = t >> 3;   // 0..15 -> node octet
    const int tc = t & 7;    // 0..7  -> channel quad

    // staging indices: h: idx = t + i*NT (0..511), node=idx>>2, kvec=idx&3
    const int snode = t >> 2;      // base node (i adds NT>>2 = 32)
    const int skvec = t & 3;
    const int wchan = t >> 2;      // 0..31
    const int wkvec = t & 3;       // 0..3

    {
        int gn = nbase + t;
        sinv[t] = (gn < N_NODES) ? 1.0f / fmaxf(g_deg[gn], 1.0f) : 0.f;
    }

    float4 hreg[4];
    float4 wreg;

    auto load_regs = [&](int kc) {
        #pragma unroll
        for (int i = 0; i < 4; i++) {
            int node = snode + i * (NT >> 2);   // +0,32,64,96
            int gn = nbase + node;
            float4 v = make_float4(0.f, 0.f, 0.f, 0.f);
            if (gn < N_NODES) {
                if (kc < 8) {
                    v = *reinterpret_cast<const float4*>(
                        &h_self[gn * IN_SELF + kc * KB + skvec * 4]);
                } else {
                    v = *reinterpret_cast<const float4*>(
                        &g_agg[gn * OUTD + (kc - 8) * KB + skvec * 4]);
                    float iv = sinv[node];
                    v.x *= iv; v.y *= iv; v.z *= iv; v.w *= iv;
                }
            }
            hreg[i] = v;
        }
        if (kc < 8)
            wreg = *reinterpret_cast<const float4*>(
                &W_self[wchan * IN_SELF + kc * KB + wkvec * 4]);
        else
            wreg = *reinterpret_cast<const float4*>(
                &W_neigh[wchan * OUTD + (kc - 8) * KB + wkvec * 4]);
    };

    auto store_smem = [&](int b) {
        #pragma unroll
        for (int i = 0; i < 4; i++) {
            int node = snode + i * (NT >> 2);
            h_s[b][skvec * 4 + 0][node] = hreg[i].x;
            h_s[b][skvec * 4 + 1][node] = hreg[i].y;
            h_s[b][skvec * 4 + 2][node] = hreg[i].z;
            h_s[b][skvec * 4 + 3][node] = hreg[i].w;
        }
        // duplicated weights: w_d[k][2c] = w_d[k][2c+1] = W[c][k]
        w_d[b][wkvec * 4 + 0][2 * wchan] = wreg.x;
        w_d[b][wkvec * 4 + 0][2 * wchan + 1] = wreg.x;
        w_d[b][wkvec * 4 + 1][2 * wchan] = wreg.y;
        w_d[b][wkvec * 4 + 1][2 * wchan + 1] = wreg.y;
        w_d[b][wkvec * 4 + 2][2 * wchan] = wreg.z;
        w_d[b][wkvec * 4 + 2][2 * wchan + 1] = wreg.z;
        w_d[b][wkvec * 4 + 3][2 * wchan] = wreg.w;
        w_d[b][wkvec * 4 + 3][2 * wchan + 1] = wreg.w;
    };

    // acc2[p][c]: p = node pair (nodes tn*8+2p, tn*8+2p+1), c = channel
    unsigned long long acc2[4][4];
    #pragma unroll
    for (int p = 0; p < 4; p++)
        #pragma unroll
        for (int c = 0; c < 4; c++) acc2[p][c] = 0ull;

    load_regs(0);
    __syncthreads();      // sinv visible, smem free
    store_smem(0);
    __syncthreads();

    #pragma unroll
    for (int kc = 0; kc < 10; kc++) {
        int b = kc & 1;
        if (kc < 9) load_regs(kc + 1);
        #pragma unroll
        for (int kk = 0; kk < KB; kk++) {
            // h pairs: 8 node values -> 4 packed pairs (free from v2.b64 loads)
            ulonglong2 hA = *reinterpret_cast<const ulonglong2*>(&h_s[b][kk][tn * 8]);
            ulonglong2 hB = *reinterpret_cast<const ulonglong2*>(&h_s[b][kk][tn * 8 + 4]);
            // w pairs: 4 duplicated channel pairs
            ulonglong2 wA = *reinterpret_cast<const ulonglong2*>(&w_d[b][kk][tc * 8]);
            ulonglong2 wB = *reinterpret_cast<const ulonglong2*>(&w_d[b][kk][tc * 8 + 4]);

            fma2(acc2[0][0], hA.x, wA.x);
            fma2(acc2[0][1], hA.x, wA.y);
            fma2(acc2[0][2], hA.x, wB.x);
            fma2(acc2[0][3], hA.x, wB.y);
            fma2(acc2[1][0], hA.y, wA.x);
            fma2(acc2[1][1], hA.y, wA.y);
            fma2(acc2[1][2], hA.y, wB.x);
            fma2(acc2[1][3], hA.y, wB.y);
            fma2(acc2[2][0], hB.x, wA.x);
            fma2(acc2[2][1], hB.x, wA.y);
            fma2(acc2[2][2], hB.x, wB.x);
            fma2(acc2[2][3], hB.x, wB.y);
            fma2(acc2[3][0], hB.y, wA.x);
            fma2(acc2[3][1], hB.y, wA.y);
            fma2(acc2[3][2], hB.y, wB.x);
            fma2(acc2[3][3], hB.y, wB.y);
        }
        if (kc < 9) store_smem(1 - b);
        __syncthreads();
    }

    // epilogue: unpack pairs, relu, STG.128 per node row
    #pragma unroll
    for (int p = 0; p < 4; p++) {
        float lo[4], hi[4];
        #pragma unroll
        for (int c = 0; c < 4; c++) {
            float2 v = *reinterpret_cast<float2*>(&acc2[p][c]);
            lo[c] = fmaxf(v.x, 0.f);
            hi[c] = fmaxf(v.y, 0.f);
        }
        int gn0 = nbase + tn * 8 + 2 * p;
        if (gn0 < N_NODES)
            *reinterpret_cast<float4*>(&out[gn0 * OUTD + tc * 4]) =
                make_float4(lo[0], lo[1], lo[2], lo[3]);
        if (gn0 + 1 < N_NODES)
            *reinterpret_cast<float4*>(&out[(gn0 + 1) * OUTD + tc * 4]) =
                make_float4(hi[0], hi[1], hi[2], hi[3]);
    }
}

extern "C" void kernel_launch(void* const* d_in, const int* in_sizes, int n_in,
                              void* d_out, int out_size) {
    const float* h_neigh       = (const float*)d_in[0];
    const float* h_self        = (const float*)d_in[1];
    const float* edge_features = (const float*)d_in[2];
    const float* W_edge        = (const float*)d_in[3];
    const float* b_edge        = (const float*)d_in[4];
    const float* W_self        = (const float*)d_in[5];
    const float* W_neigh       = (const float*)d_in[6];
    const int*   src           = (const int*)d_in[7];
    const int*   dst           = (const int*)d_in[8];
    float* out = (float*)d_out;

    void* scratch_ptr = nullptr;
    cudaGetSymbolAddress(&scratch_ptr, g_scratch);
    cudaMemsetAsync(scratch_ptr, 0, sizeof(float) * (N_NODES * OUTD + N_NODES), 0);

    edge_kernel<<<EDGE_BLOCKS, EDGE_THREADS>>>(h_neigh, edge_features,
                                               W_edge, b_edge, src, dst);

    int node_blocks = (N_NODES + BN - 1) / BN;  // 391
    node_kernel<<<node_blocks, NT>>>(h_self, W_self, W_neigh, out);
}